// round 17
// baseline (speedup 1.0000x reference)
#include <cuda_runtime.h>
#include <cstdint>

__device__ __forceinline__ float tanh_fast(float x) {
    float y;
    asm("tanh.approx.f32 %0, %1;" : "=f"(y) : "f"(x));
    return y;
}
__device__ __forceinline__ float cos_fast(float x) {
    float y;
    asm("cos.approx.ftz.f32 %0, %1;" : "=f"(y) : "f"(x));
    return y;
}

#define N_LAYERS 5
#define Q_DEPTH  2

#define GRID_T   1024
#define XMIN     (-8.0f)
#define H_STEP   0.015625f      // 16/1024
#define INV_H    64.0f          // 1/H
#define C_OFS    512.0f         // -XMIN*INV_H
#define C_MAX    1022.999f      // keep ix+1 <= 1023

// 4 MB backbone lookup table: tbl[iy][ix] = class_out(x0 = XMIN+ix*H, x1 = XMIN+iy*H)
__device__ float g_table[GRID_T * GRID_T];

// ---------------- build kernel: tabulate the classical backbone ----------------
__global__ __launch_bounds__(256)
void build_table(
    const float* __restrict__ Ws, const float* __restrict__ bs,
    const float* __restrict__ scales, const float* __restrict__ shifts,
    const float* __restrict__ Wf, const float* __restrict__ bf)
{
    // hoist all params into registers once (amortized over 8 entries/thread)
    float W[N_LAYERS][4], B[N_LAYERS][2], SC[N_LAYERS][2], SH[N_LAYERS][2];
#pragma unroll
    for (int l = 0; l < N_LAYERS; ++l) {
        W[l][0] = __ldg(&Ws[l*4+0]); W[l][1] = __ldg(&Ws[l*4+1]);
        W[l][2] = __ldg(&Ws[l*4+2]); W[l][3] = __ldg(&Ws[l*4+3]);
        B[l][0]  = __ldg(&bs[l*2+0]);     B[l][1]  = __ldg(&bs[l*2+1]);
        SC[l][0] = __ldg(&scales[l*2+0]); SC[l][1] = __ldg(&scales[l*2+1]);
        SH[l][0] = __ldg(&shifts[l*2+0]); SH[l][1] = __ldg(&shifts[l*2+1]);
    }
    const float wf0 = __ldg(&Wf[0]), wf1 = __ldg(&Wf[1]), bfv = __ldg(&bf[0]);

    const int tid = blockIdx.x * blockDim.x + threadIdx.x;
    const int stride = gridDim.x * blockDim.x;
    for (int idx = tid; idx < GRID_T * GRID_T; idx += stride) {
        int iy = idx >> 10;
        int ix = idx & (GRID_T - 1);
        float h0 = fmaf((float)ix, H_STEP, XMIN);   // x0
        float h1 = fmaf((float)iy, H_STEP, XMIN);   // x1
#pragma unroll
        for (int l = 0; l < N_LAYERS; ++l) {
            float t0 = tanh_fast(fmaf(W[l][0], h0, fmaf(W[l][1], h1, B[l][0])));
            float t1 = tanh_fast(fmaf(W[l][2], h0, fmaf(W[l][3], h1, B[l][1])));
            h0 = fmaf(t0, SC[l][0], SH[l][0]);
            h1 = fmaf(t1, SC[l][1], SH[l][1]);
        }
        g_table[idx] = fmaf(wf0, h0, fmaf(wf1, h1, bfv));
    }
}

// ---------------- main kernel: bilinear table + analytic quantum head ----------
// smem: [0]=K0 [1]=K1 [2]=K2 [3]=K3-K4 [4]=K4
__device__ __forceinline__ void build_qcoefs(float* sf, const float* __restrict__ theta)
{
    // U = prod_d [ CZ * (RY1 (x) RY0) ], real 4x4; rows 0 and 3 needed
    float U[4][4];
#pragma unroll
    for (int i = 0; i < 4; ++i)
#pragma unroll
        for (int j = 0; j < 4; ++j)
            U[i][j] = (i == j) ? 1.0f : 0.0f;

#pragma unroll
    for (int d = 0; d < Q_DEPTH; ++d) {
        float a0 = theta[d*2+0] * 0.5f;
        float a1 = theta[d*2+1] * 0.5f;
        float s0, c0, s1, c1;
        __sincosf(a0, &s0, &c0);
        __sincosf(a1, &s1, &c1);
        float ry0[2][2] = {{c0, -s0}, {s0, c0}};
        float ry1[2][2] = {{c1, -s1}, {s1, c1}};
        float M[4][4];
#pragma unroll
        for (int i = 0; i < 4; ++i)
#pragma unroll
            for (int j = 0; j < 4; ++j) {
                float acc = 0.0f;
#pragma unroll
                for (int k = 0; k < 4; ++k)
                    acc = fmaf(ry1[i>>1][k>>1] * ry0[i&1][k&1], U[k][j], acc);
                M[i][j] = acc;
            }
#pragma unroll
        for (int i = 0; i < 4; ++i)
#pragma unroll
            for (int j = 0; j < 4; ++j)
                U[i][j] = (i == 3) ? -M[i][j] : M[i][j];   // CZ flips |11> row
    }
    // q = K0 + K1 cos x0 + K2 cos x1 + K3 cos x0 cos x1 + K4 sin x0 sin x1
    float a = U[0][0]*U[0][0], b = U[0][1]*U[0][1], c = U[0][2]*U[0][2], dd = U[0][3]*U[0][3];
    float e = U[3][0]*U[3][0], f = U[3][1]*U[3][1], g = U[3][2]*U[3][2], h = U[3][3]*U[3][3];
    float cross0 = 2.0f * (U[0][1]*U[0][2] - U[0][0]*U[0][3]);
    float cross3 = 2.0f * (U[3][1]*U[3][2] - U[3][0]*U[3][3]);
    sf[0] = 0.5f * ((a + b + c + dd) - (e + f + g + h));               // K0
    sf[1] = 0.5f * ((a - b + c - dd) - (e - f + g - h));               // K1
    sf[2] = 0.5f * ((a + b - c - dd) - (e + f - g - h));               // K2
    sf[3] = 0.5f * ((a - b - c + dd) - (e - f - g + h))
          - 0.5f * (cross0 - cross3);                                  // K3 - K4
    sf[4] = 0.5f * (cross0 - cross3);                                  // K4
}

__global__ __launch_bounds__(256, 6)
void fraud_hybrid_main(
    const float4* __restrict__ x4,    // [N/2] of (x0,x1) pairs
    float2*       __restrict__ out2,  // [N/2]
    const float*  __restrict__ x_raw,
    float*        __restrict__ out_raw,
    const float*  __restrict__ theta,
    int n, int nvec)
{
    __shared__ float sf[8];
    if (threadIdx.x == 0)
        build_qcoefs(sf, theta);
    __syncthreads();
    const float K0 = sf[0], K1 = sf[1], K2 = sf[2], K34 = sf[3], K4 = sf[4];

    auto eval = [&](float x0, float x1) -> float {
        // --- backbone via bilinear table lookup ---
        float c0 = fmaf(x0, INV_H, C_OFS);
        float c1 = fmaf(x1, INV_H, C_OFS);
        c0 = fminf(fmaxf(c0, 0.0f), C_MAX);
        c1 = fminf(fmaxf(c1, 0.0f), C_MAX);
        float fx0 = floorf(c0), fy0 = floorf(c1);
        int ix = (int)fx0, iy = (int)fy0;
        float fx = c0 - fx0, fy = c1 - fy0;
        int base = iy * GRID_T + ix;
        float w00 = __ldg(&g_table[base]);
        float w01 = __ldg(&g_table[base + 1]);
        float w10 = __ldg(&g_table[base + GRID_T]);
        float w11 = __ldg(&g_table[base + GRID_T + 1]);
        float ra = fmaf(fx, w01 - w00, w00);
        float rb = fmaf(fx, w11 - w10, w10);
        float cls = fmaf(fy, rb - ra, ra);
        // --- quantum head (exact, periodic -> cannot be tabulated-clamped) ---
        float C0 = cos_fast(x0);
        float C1 = cos_fast(x1);
        float CD = cos_fast(x0 - x1);         // sin x0 sin x1 = CD - C0*C1
        float cc = C0 * C1;
        float q = fmaf(K1, C0, fmaf(K2, C1, fmaf(K34, cc, fmaf(K4, CD, K0))));
        return cls + q;
    };

    const int tid = blockIdx.x * blockDim.x + threadIdx.x;
    const int stride = gridDim.x * blockDim.x;

    for (int i = tid; i < nvec; i += stride) {
        float4 a = __ldg(&x4[i]);
        float r0 = eval(a.x, a.y);
        float r1 = eval(a.z, a.w);
        out2[i] = make_float2(r0, r1);
    }

    // tail (n odd) — defensive; N = 4M is even
    if (tid == 0 && (n & 1)) {
        int idx = n - 1;
        out_raw[idx] = eval(x_raw[2*idx], x_raw[2*idx+1]);
    }
}

extern "C" void kernel_launch(void* const* d_in, const int* in_sizes, int n_in,
                              void* d_out, int out_size) {
    const float* x      = (const float*)d_in[0];  // [N,2]
    const float* Ws     = (const float*)d_in[1];  // [5,2,2]
    const float* bs     = (const float*)d_in[2];  // [5,2]
    const float* scales = (const float*)d_in[3];  // [5,2]
    const float* shifts = (const float*)d_in[4];  // [5,2]
    const float* Wf     = (const float*)d_in[5];  // [1,2]
    const float* bf     = (const float*)d_in[6];  // [1]
    const float* theta  = (const float*)d_in[7];  // [2,2]

    const int n = out_size;
    const int nvec = n >> 1;              // float4 tiles (2 elements each)

    // 1) tabulate backbone: 1024^2 entries, 8 per thread
    build_table<<<512, 256>>>(Ws, bs, scales, shifts, Wf, bf);

    // 2) main pass: bilinear gather + analytic quantum head
    const int threads = 256;
    int blocks = 148 * 6;
    int max_blocks = (nvec + threads - 1) / threads;
    if (blocks > max_blocks) blocks = max_blocks;
    if (blocks < 1) blocks = 1;

    fraud_hybrid_main<<<blocks, threads>>>(
        (const float4*)x, (float2*)d_out, x, (float*)d_out, theta, n, nvec);
}